// round 16
// baseline (speedup 1.0000x reference)
#include <cuda_runtime.h>
#include <cuda_bf16.h>

#define Bz 64
#define Tz 256
#define Ez 128
#define Hz 256
#define Zz 1024
#define Lz 9
#define WEz 100

#define LOG0  0
#define LENS0 147456
#define LL0   147520
#define TAGS0 147584

typedef unsigned long long ull;

// ---------------- device scratch ----------------
__device__ __align__(16) float g_x[Bz*Tz*Ez];
__device__ __align__(16) float g_zx[2][4][Tz*Bz][Hz];   // [dir][gate][t*B+b][hc]
__device__ __align__(16) float g_hs[Bz*Tz*2*Hz];
__device__ __align__(16) float g_hbuf[2][2][Hz*Bz];     // [dir][parity][hc*64+row]
__device__ unsigned int g_bar2[2];

__device__ __forceinline__ float sigf(float x) { return 1.f / (1.f + __expf(-x)); }
__device__ __forceinline__ float tanhf_fast(float x) {
    float e = __expf(2.f * x);
    return 1.f - 2.f / (e + 1.f);
}

// packed f32x2 helpers
__device__ __forceinline__ ull packdup(float x) {
    ull r;
    unsigned int u = __float_as_uint(x);
    asm("mov.b64 %0, {%1, %1};" : "=l"(r) : "r"(u));
    return r;
}
__device__ __forceinline__ ull pack2(float a, float b) {
    ull r;
    asm("mov.b64 %0, {%1, %2};" : "=l"(r) : "r"(__float_as_uint(a)), "r"(__float_as_uint(b)));
    return r;
}
__device__ __forceinline__ void fma2(ull &d, ull a, ull b) {
    asm("fma.rn.f32x2 %0, %1, %2, %0;" : "+l"(d) : "l"(a), "l"(b));
}
__device__ __forceinline__ ull addp(ull a, ull b) {
    ull r;
    asm("add.rn.f32x2 %0, %1, %2;" : "=l"(r) : "l"(a), "l"(b));
    return r;
}
__device__ __forceinline__ void unpack2(ull v, float &lo, float &hi) {
    unsigned int a, b;
    asm("mov.b64 {%0, %1}, %2;" : "=r"(a), "=r"(b) : "l"(v));
    lo = __uint_as_float(a); hi = __uint_as_float(b);
}
__device__ __forceinline__ ull shfl64(ull v, int m) {
    return __shfl_xor_sync(0xffffffffu, v, m);
}

__global__ void init_kernel() { g_bar2[0] = 0u; g_bar2[1] = 0u; }

// ---------------- 1) embed: warp-per-row ----------------
__global__ void __launch_bounds__(256)
embed_kernel(const int* __restrict__ chars, const int* __restrict__ words,
             const float* __restrict__ char_emb, const float* __restrict__ word_emb,
             const float* __restrict__ W_word) {
    extern __shared__ float sW[];   // [100*128]
    int tid = threadIdx.x;
    int lane = tid & 31;
    int wrp = tid >> 5;
    for (int i = tid; i < WEz*Ez; i += 256) sW[i] = W_word[i];
    __syncthreads();

    int row0 = blockIdx.x * 128 + wrp * 16;
    for (int r = 0; r < 16; ++r) {
        int bt = row0 + r;
        int ch = chars[bt], wd = words[bt];
        float4 acc = *(const float4*)&char_emb[(long)ch * Ez + lane*4];
        float we[4];
        #pragma unroll
        for (int kk = 0; kk < 4; ++kk) {
            int k = kk*32 + lane;
            we[kk] = (k < WEz) ? word_emb[(long)wd * WEz + k] : 0.f;
        }
        #pragma unroll
        for (int kk = 0; kk < 3; ++kk) {
            #pragma unroll
            for (int l = 0; l < 32; ++l) {
                float wk = __shfl_sync(0xffffffffu, we[kk], l);
                const float* wr = &sW[(kk*32 + l)*Ez + lane*4];
                float4 w4 = *(const float4*)wr;
                acc.x = fmaf(wk, w4.x, acc.x);
                acc.y = fmaf(wk, w4.y, acc.y);
                acc.z = fmaf(wk, w4.z, acc.z);
                acc.w = fmaf(wk, w4.w, acc.w);
            }
        }
        #pragma unroll
        for (int l = 0; l < 4; ++l) {
            float wk = __shfl_sync(0xffffffffu, we[3], l);
            const float* wr = &sW[(96 + l)*Ez + lane*4];
            float4 w4 = *(const float4*)wr;
            acc.x = fmaf(wk, w4.x, acc.x);
            acc.y = fmaf(wk, w4.y, acc.y);
            acc.z = fmaf(wk, w4.z, acc.z);
            acc.w = fmaf(wk, w4.w, acc.w);
        }
        *(float4*)&g_x[bt * Ez + lane*4] = acc;
    }
}

// ---------------- 2) zx = x @ Wi + b (pipelined, coalesced epilogue) ----------------
__global__ void __launch_bounds__(256)
gemm_zx_kernel(const float* __restrict__ Wi_f, const float* __restrict__ Wi_b,
               const float* __restrict__ b_f, const float* __restrict__ b_b) {
    __shared__ float sA[8][132];
    __shared__ float sB[8][128];
    int tid = threadIdx.x;
    int bm = blockIdx.x, bn = blockIdx.y;
    int n0 = bn * 128;
    int dir = n0 >> 10;
    int n0l = n0 & 1023;
    const float* Wi   = dir ? Wi_b : Wi_f;
    const float* bias = dir ? b_b  : b_f;

    int tx = tid & 15, ty = tid >> 4;
    int ar = tid >> 1, ac = (tid & 1) * 4;
    int br = tid >> 5, bc = (tid & 31) * 4;

    ull acc[8][4] = {};

    float4 av = *(const float4*)&g_x[(bm*128 + ar)*Ez + ac];
    float4 bv = *(const float4*)&Wi[br*Zz + n0l + bc];

    for (int kk = 0; kk < Ez; kk += 8) {
        __syncthreads();
        sA[ac+0][ar] = av.x; sA[ac+1][ar] = av.y;
        sA[ac+2][ar] = av.z; sA[ac+3][ar] = av.w;
        *(float4*)&sB[br][bc] = bv;
        __syncthreads();
        if (kk + 8 < Ez) {
            av = *(const float4*)&g_x[(bm*128 + ar)*Ez + kk + 8 + ac];
            bv = *(const float4*)&Wi[(kk + 8 + br)*Zz + n0l + bc];
        }
        #pragma unroll
        for (int k = 0; k < 8; ++k) {
            float a8[8];
            *(float4*)a8     = *(const float4*)&sA[k][ty*8];
            *(float4*)(a8+4) = *(const float4*)&sA[k][ty*8+4];
            ulonglong2 b01 = *(const ulonglong2*)&sB[k][tx*8];
            ulonglong2 b23 = *(const ulonglong2*)&sB[k][tx*8+4];
            #pragma unroll
            for (int i = 0; i < 8; ++i) {
                ull ad = packdup(a8[i]);
                fma2(acc[i][0], ad, b01.x);
                fma2(acc[i][1], ad, b01.y);
                fma2(acc[i][2], ad, b23.x);
                fma2(acc[i][3], ad, b23.y);
            }
        }
    }

    int n1b = n0l + tx*8;
    int gate = n1b >> 8;
    int hc0  = n1b & 255;
    #pragma unroll
    for (int i = 0; i < 8; ++i) {
        float c8[8];
        unpack2(acc[i][0], c8[0], c8[1]);
        unpack2(acc[i][1], c8[2], c8[3]);
        unpack2(acc[i][2], c8[4], c8[5]);
        unpack2(acc[i][3], c8[6], c8[7]);
        int m = bm*128 + ty*8 + i;
        int b_ = m >> 8, t_ = m & 255;
        float* dst = &g_zx[dir][gate][t_*Bz + b_][hc0];
        float4 lo = make_float4(c8[0] + bias[n1b+0], c8[1] + bias[n1b+1],
                                c8[2] + bias[n1b+2], c8[3] + bias[n1b+3]);
        float4 hi = make_float4(c8[4] + bias[n1b+4], c8[5] + bias[n1b+5],
                                c8[6] + bias[n1b+6], c8[7] + bias[n1b+7]);
        *(float4*)dst = lo;
        *(float4*)(dst + 4) = hi;
    }
}

// ---------------- 3) persistent biLSTM: R11 best configuration (verbatim) ----------------
#define NBLK_DIR 64
__global__ void __launch_bounds__(256, 1)
lstm_kernel(const float* __restrict__ Wh_f, const float* __restrict__ Wh_b) {
    extern __shared__ float sm[];
    float* sh = sm;              // [256][68]  69632 B
    int tid = threadIdx.x;
    int dir = blockIdx.x >> 6;
    int cb  = blockIdx.x & 63;
    const float* Wh = dir ? Wh_b : Wh_f;

    int kg  = tid & 15;          // k-slice
    int hcg = (tid >> 4) & 3;    // hc column within block
    int rg  = tid >> 6;          // row group
    int hc  = cb*4 + hcg;
    int myrow = rg*16 + kg;
    int p1 = kg & 1, p2 = kg & 2, p4 = kg & 4, p8 = kg & 8;

    // preload weights into registers (k = q*16 + kg)
    ull w01[16], w23[16];
    #pragma unroll
    for (int q = 0; q < 16; ++q) {
        int k = q*16 + kg;
        w01[q] = pack2(Wh[k*Zz + 0*256 + hc], Wh[k*Zz + 1*256 + hc]);
        w23[q] = pack2(Wh[k*Zz + 2*256 + hc], Wh[k*Zz + 3*256 + hc]);
    }

    const float* ph_base = sh + (unsigned)kg*68u + (unsigned)rg*16u;
    unsigned int* barp = &g_bar2[dir];
    unsigned zrow0 = (unsigned)((dir ? Tz-1 : 0)*Bz + myrow);

    float c_state = 0.f;
    float z0 = g_zx[dir][0][zrow0][hc];
    float z1 = g_zx[dir][1][zrow0][hc];
    float z2 = g_zx[dir][2][zrow0][hc];
    float z3 = g_zx[dir][3][zrow0][hc];
    float zn0 = z0, zn1 = z1, zn2 = z2, zn3 = z3;

    for (int step = 0; step < Tz; ++step) {
        int t = dir ? (Tz - 1 - step) : step;

        if (step > 0) {
            // plain LDG -> STS copy of previous h
            const float4* src = (const float4*)&g_hbuf[dir][step & 1][0];
            #pragma unroll
            for (int it = 0; it < 16; ++it) {
                int i4 = it*256 + tid;
                float4 v = src[i4];
                int hcI = i4 >> 4, r4 = i4 & 15;
                *(float4*)&sh[hcI*68 + r4*4] = v;
            }
        }
        __syncthreads();

        ull acc01[16] = {0ull,0ull,0ull,0ull,0ull,0ull,0ull,0ull,
                         0ull,0ull,0ull,0ull,0ull,0ull,0ull,0ull};
        ull acc23[16] = {0ull,0ull,0ull,0ull,0ull,0ull,0ull,0ull,
                         0ull,0ull,0ull,0ull,0ull,0ull,0ull,0ull};

        if (step > 0) {
            const float* ph = ph_base;
            #pragma unroll
            for (int q = 0; q < 16; ++q) {
                float4 h0 = *(const float4*)(ph + 0);
                float4 h1 = *(const float4*)(ph + 4);
                float4 h2 = *(const float4*)(ph + 8);
                float4 h3 = *(const float4*)(ph + 12);
                ph += 16*68;
                ull wa = w01[q], wb = w23[q];
                ull hp;
                hp = packdup(h0.x); fma2(acc01[0],  hp, wa); fma2(acc23[0],  hp, wb);
                hp = packdup(h0.y); fma2(acc01[1],  hp, wa); fma2(acc23[1],  hp, wb);
                hp = packdup(h0.z); fma2(acc01[2],  hp, wa); fma2(acc23[2],  hp, wb);
                hp = packdup(h0.w); fma2(acc01[3],  hp, wa); fma2(acc23[3],  hp, wb);
                hp = packdup(h1.x); fma2(acc01[4],  hp, wa); fma2(acc23[4],  hp, wb);
                hp = packdup(h1.y); fma2(acc01[5],  hp, wa); fma2(acc23[5],  hp, wb);
                hp = packdup(h1.z); fma2(acc01[6],  hp, wa); fma2(acc23[6],  hp, wb);
                hp = packdup(h1.w); fma2(acc01[7],  hp, wa); fma2(acc23[7],  hp, wb);
                hp = packdup(h2.x); fma2(acc01[8],  hp, wa); fma2(acc23[8],  hp, wb);
                hp = packdup(h2.y); fma2(acc01[9],  hp, wa); fma2(acc23[9],  hp, wb);
                hp = packdup(h2.z); fma2(acc01[10], hp, wa); fma2(acc23[10], hp, wb);
                hp = packdup(h2.w); fma2(acc01[11], hp, wa); fma2(acc23[11], hp, wb);
                hp = packdup(h3.x); fma2(acc01[12], hp, wa); fma2(acc23[12], hp, wb);
                hp = packdup(h3.y); fma2(acc01[13], hp, wa); fma2(acc23[13], hp, wb);
                hp = packdup(h3.z); fma2(acc01[14], hp, wa); fma2(acc23[14], hp, wb);
                hp = packdup(h3.w); fma2(acc01[15], hp, wa); fma2(acc23[15], hp, wb);
            }
        }

        // select-exchange reduction over 16 kg lanes (intra-warp, masks 1/2/4/8)
        ull b01[8], b23[8];
        #pragma unroll
        for (int j = 0; j < 8; ++j) {
            ull s = p1 ? acc01[2*j] : acc01[2*j+1];
            ull r = shfl64(s, 1);
            b01[j] = addp(p1 ? acc01[2*j+1] : acc01[2*j], r);
            ull s2 = p1 ? acc23[2*j] : acc23[2*j+1];
            ull r2 = shfl64(s2, 1);
            b23[j] = addp(p1 ? acc23[2*j+1] : acc23[2*j], r2);
        }
        ull c01[4], c23[4];
        #pragma unroll
        for (int j = 0; j < 4; ++j) {
            ull s = p2 ? b01[2*j] : b01[2*j+1];
            ull r = shfl64(s, 2);
            c01[j] = addp(p2 ? b01[2*j+1] : b01[2*j], r);
            ull s2 = p2 ? b23[2*j] : b23[2*j+1];
            ull r2 = shfl64(s2, 2);
            c23[j] = addp(p2 ? b23[2*j+1] : b23[2*j], r2);
        }
        ull d01[2], d23[2];
        #pragma unroll
        for (int j = 0; j < 2; ++j) {
            ull s = p4 ? c01[2*j] : c01[2*j+1];
            ull r = shfl64(s, 4);
            d01[j] = addp(p4 ? c01[2*j+1] : c01[2*j], r);
            ull s2 = p4 ? c23[2*j] : c23[2*j+1];
            ull r2 = shfl64(s2, 4);
            d23[j] = addp(p4 ? c23[2*j+1] : c23[2*j], r2);
        }
        ull e01, e23;
        {
            ull s = p8 ? d01[0] : d01[1];
            ull r = shfl64(s, 8);
            e01 = addp(p8 ? d01[1] : d01[0], r);
            ull s2 = p8 ? d23[0] : d23[1];
            ull r2 = shfl64(s2, 8);
            e23 = addp(p8 ? d23[1] : d23[0], r2);
        }

        float f0, f1, f2, f3;
        unpack2(e01, f0, f1);
        unpack2(e23, f2, f3);

        float zi = z0 + f0;
        float zf = z1 + f1;
        float zg = z2 + f2;
        float zo = z3 + f3;

        float ig = sigf(zi), fg = sigf(zf), gg = tanhf_fast(zg), og = sigf(zo);
        c_state = fg * c_state + ig * gg;
        float h = og * tanhf_fast(c_state);

        g_hbuf[dir][(step + 1) & 1][hc*Bz + myrow] = h;
        __syncthreads();   // all h stores done; also protects sh write-after-read

        if (tid == 0)
            asm volatile("red.release.gpu.global.add.u32 [%0], %1;"
                         :: "l"(barp), "r"(1u) : "memory");

        // barrier shadow work (per-thread, before own poll)
        g_hs[(unsigned)(myrow*Tz + t)*512u + dir*Hz + hc] = h;
        if (step + 1 < Tz) {
            int tn = dir ? (Tz - 2 - step) : (step + 1);
            unsigned zr = (unsigned)(tn*Bz + myrow);
            zn0 = g_zx[dir][0][zr][hc];
            zn1 = g_zx[dir][1][zr][hc];
            zn2 = g_zx[dir][2][zr][hc];
            zn3 = g_zx[dir][3][zr][hc];
        }

        // distributed poll: every thread waits on the counter itself
        {
            unsigned target = (unsigned)NBLK_DIR * (unsigned)(step + 1);
            unsigned v;
            do {
                asm volatile("ld.global.acquire.gpu.u32 %0, [%1];" : "=r"(v) : "l"(barp));
            } while (v < target);
        }
        z0 = zn0; z1 = zn1; z2 = zn2; z3 = zn3;
    }
}

// ---------------- 4) logits = hs @ W_out + b_out (split-k x4, 512 blocks) ----------------
__global__ void __launch_bounds__(128)
logits_kernel(const float* __restrict__ W_out, const float* __restrict__ b_out,
              float* __restrict__ out) {
    __shared__ float sW[512*Lz];
    __shared__ float sb[Lz];
    int tid = threadIdx.x;
    for (int i = tid; i < 512*Lz; i += 128) sW[i] = W_out[i];
    if (tid < Lz) sb[tid] = b_out[tid];
    __syncthreads();

    int gid = blockIdx.x * 128 + tid;   // 0..65535
    int row = gid >> 2;                 // b*T + t (0..16383)
    int kq  = gid & 3;                  // k-quarter
    const float4* hrow = (const float4*)(g_hs + (unsigned)row*512u + (unsigned)kq*128u);
    const float* sWq = sW + kq*128*Lz;

    float acc[Lz] = {};
    #pragma unroll 8
    for (int k4 = 0; k4 < 32; ++k4) {
        float4 h4 = hrow[k4];
        int k = k4*4;
        float hv[4] = {h4.x, h4.y, h4.z, h4.w};
        #pragma unroll
        for (int e = 0; e < 4; ++e)
            #pragma unroll
            for (int c = 0; c < Lz; ++c)
                acc[c] = fmaf(hv[e], sWq[(k+e)*Lz + c], acc[c]);
    }
    // reduce across the 4 kq lanes (consecutive lanes share a row)
    #pragma unroll
    for (int c = 0; c < Lz; ++c) {
        acc[c] += __shfl_xor_sync(0xffffffffu, acc[c], 1);
        acc[c] += __shfl_xor_sync(0xffffffffu, acc[c], 2);
    }
    if (kq == 0) {
        #pragma unroll
        for (int c = 0; c < Lz; ++c)
            out[LOG0 + (unsigned)row*Lz + c] = acc[c] + sb[c];
    }
}

// ---------------- 5) CRF: 2 warps (forward || viterbi) ----------------
__global__ void crf_kernel(const int* __restrict__ chars, const int* __restrict__ labels,
                           const float* __restrict__ trans, float* __restrict__ out) {
    __shared__ float slog[Tz*Lz];
    __shared__ unsigned char bps[255][16];
    int b = blockIdx.x;
    int tid = threadIdx.x;
    int wid = tid >> 5;
    int lane = tid & 31;
    const float* logits = out + LOG0 + (unsigned)b*Tz*Lz;

    for (int i = tid; i < Tz*Lz; i += 64) slog[i] = logits[i];

    float tr[Lz];
    if (lane < Lz) {
        #pragma unroll
        for (int i = 0; i < Lz; ++i) tr[i] = trans[i*Lz + lane];
    }

    int cnt = 0;
    for (int t = lane; t < Tz; t += 32) cnt += (chars[b*Tz + t] != 0);
    #pragma unroll
    for (int off = 16; off; off >>= 1) cnt += __shfl_xor_sync(0xffffffffu, cnt, off);
    int len = cnt;

    __syncthreads();

    if (wid == 0) {
        float sc = 0.f;
        for (int t = lane; t < Tz; t += 32) {
            int lab = labels[b*Tz + t];
            if (t < len) {
                sc += slog[t*Lz + lab];
                if (t >= 1) sc += trans[labels[b*Tz + t - 1]*Lz + lab];
            }
        }
        #pragma unroll
        for (int off = 16; off; off >>= 1) sc += __shfl_xor_sync(0xffffffffu, sc, off);

        float al = (lane < Lz) ? slog[lane] : -1e30f;
        for (int t = 1; t < Tz; ++t) {
            float lg = (lane < Lz) ? slog[t*Lz + lane] : 0.f;
            float vals[Lz];
            float m1 = -1e30f;
            #pragma unroll
            for (int i = 0; i < Lz; ++i) {
                float ai = __shfl_sync(0xffffffffu, al, i);
                float x1 = ai + tr[i];
                vals[i] = x1;
                m1 = fmaxf(m1, x1);
            }
            float s = 0.f;
            #pragma unroll
            for (int i = 0; i < Lz; ++i) s += expf(vals[i] - m1);
            float nal = m1 + logf(s) + lg;
            if (lane < Lz && t < len) al = nal;
        }
        float m = -1e30f;
        #pragma unroll
        for (int i = 0; i < Lz; ++i) m = fmaxf(m, __shfl_sync(0xffffffffu, al, i));
        float s = 0.f;
        #pragma unroll
        for (int i = 0; i < Lz; ++i) s += expf(__shfl_sync(0xffffffffu, al, i) - m);
        float lognorm = m + logf(s);
        if (lane == 0) {
            out[LL0 + b] = sc - lognorm;
            out[LENS0 + b] = (float)len;
        }
    } else {
        float av = (lane < Lz) ? slog[lane] : -1e30f;
        for (int t = 1; t < Tz; ++t) {
            float lg = (lane < Lz) ? slog[t*Lz + lane] : 0.f;
            float m2 = -1e30f;
            int arg = 0;
            #pragma unroll
            for (int i = 0; i < Lz; ++i) {
                float vi = __shfl_sync(0xffffffffu, av, i);
                float x2 = vi + tr[i];
                if (x2 > m2) { m2 = x2; arg = i; }
            }
            float nav = m2 + lg;
            bool act = (t < len);
            if (lane < Lz) {
                if (act) {
                    av = nav;
                    bps[t-1][lane] = (unsigned char)arg;
                } else {
                    bps[t-1][lane] = (unsigned char)lane;
                }
            }
        }
        __syncwarp();
        float bestv = -1e30f; int bestidx = 0;
        #pragma unroll
        for (int i = 0; i < Lz; ++i) {
            float vi = __shfl_sync(0xffffffffu, av, i);
            if (vi > bestv) { bestv = vi; bestidx = i; }
        }
        if (lane == 0) {
            int tag = bestidx;
            out[TAGS0 + b*Tz + 255] = (float)tag;
            for (int k = 254; k >= 0; --k) {
                tag = bps[k][tag];
                out[TAGS0 + b*Tz + k] = (float)tag;
            }
        }
    }
}

// ---------------- launch ----------------
extern "C" void kernel_launch(void* const* d_in, const int* in_sizes, int n_in,
                              void* d_out, int out_size) {
    const int*   chars    = (const int*)d_in[0];
    const int*   words    = (const int*)d_in[1];
    const int*   labels   = (const int*)d_in[2];
    const float* char_emb = (const float*)d_in[3];
    const float* word_emb = (const float*)d_in[4];
    const float* W_word   = (const float*)d_in[5];
    const float* Wi_f     = (const float*)d_in[6];
    const float* Wh_f     = (const float*)d_in[7];
    const float* b_f      = (const float*)d_in[8];
    const float* Wi_b     = (const float*)d_in[9];
    const float* Wh_b     = (const float*)d_in[10];
    const float* b_b      = (const float*)d_in[11];
    const float* W_out    = (const float*)d_in[12];
    const float* b_out    = (const float*)d_in[13];
    const float* trans    = (const float*)d_in[14];
    float* out = (float*)d_out;

    cudaFuncSetAttribute(embed_kernel, cudaFuncAttributeMaxDynamicSharedMemorySize, 51200);
    cudaFuncSetAttribute(lstm_kernel,  cudaFuncAttributeMaxDynamicSharedMemorySize, 73728);

    init_kernel<<<1, 1>>>();
    embed_kernel<<<128, 256, 51200>>>(chars, words, char_emb, word_emb, W_word);
    gemm_zx_kernel<<<dim3(128, 16), 256>>>(Wi_f, Wi_b, b_f, b_b);
    lstm_kernel<<<128, 256, 73728>>>(Wh_f, Wh_b);
    logits_kernel<<<512, 128>>>(W_out, b_out, out);
    crf_kernel<<<Bz, 64>>>(chars, labels, trans, out);
}

// round 17
// speedup vs baseline: 1.0371x; 1.0371x over previous
#include <cuda_runtime.h>
#include <cuda_bf16.h>

#define Bz 64
#define Tz 256
#define Ez 128
#define Hz 256
#define Zz 1024
#define Lz 9
#define WEz 100

#define LOG0  0
#define LENS0 147456
#define LL0   147520
#define TAGS0 147584

typedef unsigned long long ull;

// ---------------- device scratch ----------------
__device__ __align__(16) float g_x[Bz*Tz*Ez];
__device__ __align__(16) float g_zx[2][4][Tz*Bz][Hz];   // [dir][gate][t*B+b][hc]
__device__ __align__(16) float g_hs[Bz*Tz*2*Hz];
__device__ __align__(16) float g_hbuf[2][2][Hz*Bz];     // [dir][parity][hc*64+row]
__device__ unsigned int g_bar2[2];

__device__ __forceinline__ float sigf(float x) { return 1.f / (1.f + __expf(-x)); }
__device__ __forceinline__ float tanhf_fast(float x) {
    float e = __expf(2.f * x);
    return 1.f - 2.f / (e + 1.f);
}

// packed f32x2 helpers
__device__ __forceinline__ ull packdup(float x) {
    ull r;
    unsigned int u = __float_as_uint(x);
    asm("mov.b64 %0, {%1, %1};" : "=l"(r) : "r"(u));
    return r;
}
__device__ __forceinline__ ull pack2(float a, float b) {
    ull r;
    asm("mov.b64 %0, {%1, %2};" : "=l"(r) : "r"(__float_as_uint(a)), "r"(__float_as_uint(b)));
    return r;
}
__device__ __forceinline__ void fma2(ull &d, ull a, ull b) {
    asm("fma.rn.f32x2 %0, %1, %2, %0;" : "+l"(d) : "l"(a), "l"(b));
}
__device__ __forceinline__ ull addp(ull a, ull b) {
    ull r;
    asm("add.rn.f32x2 %0, %1, %2;" : "=l"(r) : "l"(a), "l"(b));
    return r;
}
__device__ __forceinline__ void unpack2(ull v, float &lo, float &hi) {
    unsigned int a, b;
    asm("mov.b64 {%0, %1}, %2;" : "=r"(a), "=r"(b) : "l"(v));
    lo = __uint_as_float(a); hi = __uint_as_float(b);
}
__device__ __forceinline__ ull shfl64(ull v, int m) {
    return __shfl_xor_sync(0xffffffffu, v, m);
}

__global__ void init_kernel() { g_bar2[0] = 0u; g_bar2[1] = 0u; }

// ---------------- 1) embed: warp-per-row ----------------
__global__ void __launch_bounds__(256)
embed_kernel(const int* __restrict__ chars, const int* __restrict__ words,
             const float* __restrict__ char_emb, const float* __restrict__ word_emb,
             const float* __restrict__ W_word) {
    extern __shared__ float sW[];   // [100*128]
    int tid = threadIdx.x;
    int lane = tid & 31;
    int wrp = tid >> 5;
    for (int i = tid; i < WEz*Ez; i += 256) sW[i] = W_word[i];
    __syncthreads();

    int row0 = blockIdx.x * 128 + wrp * 16;
    for (int r = 0; r < 16; ++r) {
        int bt = row0 + r;
        int ch = chars[bt], wd = words[bt];
        float4 acc = *(const float4*)&char_emb[(long)ch * Ez + lane*4];
        float we[4];
        #pragma unroll
        for (int kk = 0; kk < 4; ++kk) {
            int k = kk*32 + lane;
            we[kk] = (k < WEz) ? word_emb[(long)wd * WEz + k] : 0.f;
        }
        #pragma unroll
        for (int kk = 0; kk < 3; ++kk) {
            #pragma unroll
            for (int l = 0; l < 32; ++l) {
                float wk = __shfl_sync(0xffffffffu, we[kk], l);
                const float* wr = &sW[(kk*32 + l)*Ez + lane*4];
                float4 w4 = *(const float4*)wr;
                acc.x = fmaf(wk, w4.x, acc.x);
                acc.y = fmaf(wk, w4.y, acc.y);
                acc.z = fmaf(wk, w4.z, acc.z);
                acc.w = fmaf(wk, w4.w, acc.w);
            }
        }
        #pragma unroll
        for (int l = 0; l < 4; ++l) {
            float wk = __shfl_sync(0xffffffffu, we[3], l);
            const float* wr = &sW[(96 + l)*Ez + lane*4];
            float4 w4 = *(const float4*)wr;
            acc.x = fmaf(wk, w4.x, acc.x);
            acc.y = fmaf(wk, w4.y, acc.y);
            acc.z = fmaf(wk, w4.z, acc.z);
            acc.w = fmaf(wk, w4.w, acc.w);
        }
        *(float4*)&g_x[bt * Ez + lane*4] = acc;
    }
}

// ---------------- 2) zx = x @ Wi + b (pipelined, coalesced epilogue) ----------------
__global__ void __launch_bounds__(256)
gemm_zx_kernel(const float* __restrict__ Wi_f, const float* __restrict__ Wi_b,
               const float* __restrict__ b_f, const float* __restrict__ b_b) {
    __shared__ float sA[8][132];
    __shared__ float sB[8][128];
    int tid = threadIdx.x;
    int bm = blockIdx.x, bn = blockIdx.y;
    int n0 = bn * 128;
    int dir = n0 >> 10;
    int n0l = n0 & 1023;
    const float* Wi   = dir ? Wi_b : Wi_f;
    const float* bias = dir ? b_b  : b_f;

    int tx = tid & 15, ty = tid >> 4;
    int ar = tid >> 1, ac = (tid & 1) * 4;
    int br = tid >> 5, bc = (tid & 31) * 4;

    ull acc[8][4] = {};

    float4 av = *(const float4*)&g_x[(bm*128 + ar)*Ez + ac];
    float4 bv = *(const float4*)&Wi[br*Zz + n0l + bc];

    for (int kk = 0; kk < Ez; kk += 8) {
        __syncthreads();
        sA[ac+0][ar] = av.x; sA[ac+1][ar] = av.y;
        sA[ac+2][ar] = av.z; sA[ac+3][ar] = av.w;
        *(float4*)&sB[br][bc] = bv;
        __syncthreads();
        if (kk + 8 < Ez) {
            av = *(const float4*)&g_x[(bm*128 + ar)*Ez + kk + 8 + ac];
            bv = *(const float4*)&Wi[(kk + 8 + br)*Zz + n0l + bc];
        }
        #pragma unroll
        for (int k = 0; k < 8; ++k) {
            float a8[8];
            *(float4*)a8     = *(const float4*)&sA[k][ty*8];
            *(float4*)(a8+4) = *(const float4*)&sA[k][ty*8+4];
            ulonglong2 b01 = *(const ulonglong2*)&sB[k][tx*8];
            ulonglong2 b23 = *(const ulonglong2*)&sB[k][tx*8+4];
            #pragma unroll
            for (int i = 0; i < 8; ++i) {
                ull ad = packdup(a8[i]);
                fma2(acc[i][0], ad, b01.x);
                fma2(acc[i][1], ad, b01.y);
                fma2(acc[i][2], ad, b23.x);
                fma2(acc[i][3], ad, b23.y);
            }
        }
    }

    int n1b = n0l + tx*8;
    int gate = n1b >> 8;
    int hc0  = n1b & 255;
    #pragma unroll
    for (int i = 0; i < 8; ++i) {
        float c8[8];
        unpack2(acc[i][0], c8[0], c8[1]);
        unpack2(acc[i][1], c8[2], c8[3]);
        unpack2(acc[i][2], c8[4], c8[5]);
        unpack2(acc[i][3], c8[6], c8[7]);
        int m = bm*128 + ty*8 + i;
        int b_ = m >> 8, t_ = m & 255;
        float* dst = &g_zx[dir][gate][t_*Bz + b_][hc0];
        float4 lo = make_float4(c8[0] + bias[n1b+0], c8[1] + bias[n1b+1],
                                c8[2] + bias[n1b+2], c8[3] + bias[n1b+3]);
        float4 hi = make_float4(c8[4] + bias[n1b+4], c8[5] + bias[n1b+5],
                                c8[6] + bias[n1b+6], c8[7] + bias[n1b+7]);
        *(float4*)dst = lo;
        *(float4*)(dst + 4) = hi;
    }
}

// ---------------- 3) persistent biLSTM: R11 best configuration (verbatim) ----------------
#define NBLK_DIR 64
__global__ void __launch_bounds__(256, 1)
lstm_kernel(const float* __restrict__ Wh_f, const float* __restrict__ Wh_b) {
    extern __shared__ float sm[];
    float* sh = sm;              // [256][68]  69632 B
    int tid = threadIdx.x;
    int dir = blockIdx.x >> 6;
    int cb  = blockIdx.x & 63;
    const float* Wh = dir ? Wh_b : Wh_f;

    int kg  = tid & 15;          // k-slice
    int hcg = (tid >> 4) & 3;    // hc column within block
    int rg  = tid >> 6;          // row group
    int hc  = cb*4 + hcg;
    int myrow = rg*16 + kg;
    int p1 = kg & 1, p2 = kg & 2, p4 = kg & 4, p8 = kg & 8;

    // preload weights into registers (k = q*16 + kg)
    ull w01[16], w23[16];
    #pragma unroll
    for (int q = 0; q < 16; ++q) {
        int k = q*16 + kg;
        w01[q] = pack2(Wh[k*Zz + 0*256 + hc], Wh[k*Zz + 1*256 + hc]);
        w23[q] = pack2(Wh[k*Zz + 2*256 + hc], Wh[k*Zz + 3*256 + hc]);
    }

    const float* ph_base = sh + (unsigned)kg*68u + (unsigned)rg*16u;
    unsigned int* barp = &g_bar2[dir];
    unsigned zrow0 = (unsigned)((dir ? Tz-1 : 0)*Bz + myrow);

    float c_state = 0.f;
    float z0 = g_zx[dir][0][zrow0][hc];
    float z1 = g_zx[dir][1][zrow0][hc];
    float z2 = g_zx[dir][2][zrow0][hc];
    float z3 = g_zx[dir][3][zrow0][hc];
    float zn0 = z0, zn1 = z1, zn2 = z2, zn3 = z3;

    for (int step = 0; step < Tz; ++step) {
        int t = dir ? (Tz - 1 - step) : step;

        if (step > 0) {
            // plain LDG -> STS copy of previous h
            const float4* src = (const float4*)&g_hbuf[dir][step & 1][0];
            #pragma unroll
            for (int it = 0; it < 16; ++it) {
                int i4 = it*256 + tid;
                float4 v = src[i4];
                int hcI = i4 >> 4, r4 = i4 & 15;
                *(float4*)&sh[hcI*68 + r4*4] = v;
            }
        }
        __syncthreads();

        ull acc01[16] = {0ull,0ull,0ull,0ull,0ull,0ull,0ull,0ull,
                         0ull,0ull,0ull,0ull,0ull,0ull,0ull,0ull};
        ull acc23[16] = {0ull,0ull,0ull,0ull,0ull,0ull,0ull,0ull,
                         0ull,0ull,0ull,0ull,0ull,0ull,0ull,0ull};

        if (step > 0) {
            const float* ph = ph_base;
            #pragma unroll
            for (int q = 0; q < 16; ++q) {
                float4 h0 = *(const float4*)(ph + 0);
                float4 h1 = *(const float4*)(ph + 4);
                float4 h2 = *(const float4*)(ph + 8);
                float4 h3 = *(const float4*)(ph + 12);
                ph += 16*68;
                ull wa = w01[q], wb = w23[q];
                ull hp;
                hp = packdup(h0.x); fma2(acc01[0],  hp, wa); fma2(acc23[0],  hp, wb);
                hp = packdup(h0.y); fma2(acc01[1],  hp, wa); fma2(acc23[1],  hp, wb);
                hp = packdup(h0.z); fma2(acc01[2],  hp, wa); fma2(acc23[2],  hp, wb);
                hp = packdup(h0.w); fma2(acc01[3],  hp, wa); fma2(acc23[3],  hp, wb);
                hp = packdup(h1.x); fma2(acc01[4],  hp, wa); fma2(acc23[4],  hp, wb);
                hp = packdup(h1.y); fma2(acc01[5],  hp, wa); fma2(acc23[5],  hp, wb);
                hp = packdup(h1.z); fma2(acc01[6],  hp, wa); fma2(acc23[6],  hp, wb);
                hp = packdup(h1.w); fma2(acc01[7],  hp, wa); fma2(acc23[7],  hp, wb);
                hp = packdup(h2.x); fma2(acc01[8],  hp, wa); fma2(acc23[8],  hp, wb);
                hp = packdup(h2.y); fma2(acc01[9],  hp, wa); fma2(acc23[9],  hp, wb);
                hp = packdup(h2.z); fma2(acc01[10], hp, wa); fma2(acc23[10], hp, wb);
                hp = packdup(h2.w); fma2(acc01[11], hp, wa); fma2(acc23[11], hp, wb);
                hp = packdup(h3.x); fma2(acc01[12], hp, wa); fma2(acc23[12], hp, wb);
                hp = packdup(h3.y); fma2(acc01[13], hp, wa); fma2(acc23[13], hp, wb);
                hp = packdup(h3.z); fma2(acc01[14], hp, wa); fma2(acc23[14], hp, wb);
                hp = packdup(h3.w); fma2(acc01[15], hp, wa); fma2(acc23[15], hp, wb);
            }
        }

        // select-exchange reduction over 16 kg lanes (intra-warp, masks 1/2/4/8)
        ull b01[8], b23[8];
        #pragma unroll
        for (int j = 0; j < 8; ++j) {
            ull s = p1 ? acc01[2*j] : acc01[2*j+1];
            ull r = shfl64(s, 1);
            b01[j] = addp(p1 ? acc01[2*j+1] : acc01[2*j], r);
            ull s2 = p1 ? acc23[2*j] : acc23[2*j+1];
            ull r2 = shfl64(s2, 1);
            b23[j] = addp(p1 ? acc23[2*j+1] : acc23[2*j], r2);
        }
        ull c01[4], c23[4];
        #pragma unroll
        for (int j = 0; j < 4; ++j) {
            ull s = p2 ? b01[2*j] : b01[2*j+1];
            ull r = shfl64(s, 2);
            c01[j] = addp(p2 ? b01[2*j+1] : b01[2*j], r);
            ull s2 = p2 ? b23[2*j] : b23[2*j+1];
            ull r2 = shfl64(s2, 2);
            c23[j] = addp(p2 ? b23[2*j+1] : b23[2*j], r2);
        }
        ull d01[2], d23[2];
        #pragma unroll
        for (int j = 0; j < 2; ++j) {
            ull s = p4 ? c01[2*j] : c01[2*j+1];
            ull r = shfl64(s, 4);
            d01[j] = addp(p4 ? c01[2*j+1] : c01[2*j], r);
            ull s2 = p4 ? c23[2*j] : c23[2*j+1];
            ull r2 = shfl64(s2, 4);
            d23[j] = addp(p4 ? c23[2*j+1] : c23[2*j], r2);
        }
        ull e01, e23;
        {
            ull s = p8 ? d01[0] : d01[1];
            ull r = shfl64(s, 8);
            e01 = addp(p8 ? d01[1] : d01[0], r);
            ull s2 = p8 ? d23[0] : d23[1];
            ull r2 = shfl64(s2, 8);
            e23 = addp(p8 ? d23[1] : d23[0], r2);
        }

        float f0, f1, f2, f3;
        unpack2(e01, f0, f1);
        unpack2(e23, f2, f3);

        float zi = z0 + f0;
        float zf = z1 + f1;
        float zg = z2 + f2;
        float zo = z3 + f3;

        float ig = sigf(zi), fg = sigf(zf), gg = tanhf_fast(zg), og = sigf(zo);
        c_state = fg * c_state + ig * gg;
        float h = og * tanhf_fast(c_state);

        g_hbuf[dir][(step + 1) & 1][hc*Bz + myrow] = h;
        __syncthreads();   // all h stores done; also protects sh write-after-read

        if (tid == 0)
            asm volatile("red.release.gpu.global.add.u32 [%0], %1;"
                         :: "l"(barp), "r"(1u) : "memory");

        // barrier shadow work (per-thread, before own poll)
        g_hs[(unsigned)(myrow*Tz + t)*512u + dir*Hz + hc] = h;
        if (step + 1 < Tz) {
            int tn = dir ? (Tz - 2 - step) : (step + 1);
            unsigned zr = (unsigned)(tn*Bz + myrow);
            zn0 = g_zx[dir][0][zr][hc];
            zn1 = g_zx[dir][1][zr][hc];
            zn2 = g_zx[dir][2][zr][hc];
            zn3 = g_zx[dir][3][zr][hc];
        }

        // distributed poll: every thread waits on the counter itself
        {
            unsigned target = (unsigned)NBLK_DIR * (unsigned)(step + 1);
            unsigned v;
            do {
                asm volatile("ld.global.acquire.gpu.u32 %0, [%1];" : "=r"(v) : "l"(barp));
            } while (v < target);
        }
        z0 = zn0; z1 = zn1; z2 = zn2; z3 = zn3;
    }
}

// ---------------- 4) logits = hs @ W_out + b_out (128 blocks) ----------------
__global__ void __launch_bounds__(128)
logits_kernel(const float* __restrict__ W_out, const float* __restrict__ b_out,
              float* __restrict__ out) {
    __shared__ float sW[512*Lz];
    __shared__ float sb[Lz];
    int tid = threadIdx.x;
    for (int i = tid; i < 512*Lz; i += 128) sW[i] = W_out[i];
    if (tid < Lz) sb[tid] = b_out[tid];
    __syncthreads();
    int row = blockIdx.x * 128 + tid;   // b*T + t
    const float4* hrow = (const float4*)(g_hs + (unsigned)row*512u);
    float acc[Lz] = {};
    for (int k4 = 0; k4 < 128; ++k4) {
        float4 h4 = hrow[k4];
        int k = k4*4;
        float hv[4] = {h4.x, h4.y, h4.z, h4.w};
        #pragma unroll
        for (int e = 0; e < 4; ++e)
            #pragma unroll
            for (int c = 0; c < Lz; ++c)
                acc[c] = fmaf(hv[e], sW[(k+e)*Lz + c], acc[c]);
    }
    #pragma unroll
    for (int c = 0; c < Lz; ++c)
        out[LOG0 + (unsigned)row*Lz + c] = acc[c] + sb[c];
}

// ---------------- 5) CRF: 2 warps (forward || viterbi) ----------------
__global__ void crf_kernel(const int* __restrict__ chars, const int* __restrict__ labels,
                           const float* __restrict__ trans, float* __restrict__ out) {
    __shared__ float slog[Tz*Lz];
    __shared__ unsigned char bps[255][16];
    int b = blockIdx.x;
    int tid = threadIdx.x;
    int wid = tid >> 5;
    int lane = tid & 31;
    const float* logits = out + LOG0 + (unsigned)b*Tz*Lz;

    for (int i = tid; i < Tz*Lz; i += 64) slog[i] = logits[i];

    float tr[Lz];
    if (lane < Lz) {
        #pragma unroll
        for (int i = 0; i < Lz; ++i) tr[i] = trans[i*Lz + lane];
    }

    int cnt = 0;
    for (int t = lane; t < Tz; t += 32) cnt += (chars[b*Tz + t] != 0);
    #pragma unroll
    for (int off = 16; off; off >>= 1) cnt += __shfl_xor_sync(0xffffffffu, cnt, off);
    int len = cnt;

    __syncthreads();

    if (wid == 0) {
        float sc = 0.f;
        for (int t = lane; t < Tz; t += 32) {
            int lab = labels[b*Tz + t];
            if (t < len) {
                sc += slog[t*Lz + lab];
                if (t >= 1) sc += trans[labels[b*Tz + t - 1]*Lz + lab];
            }
        }
        #pragma unroll
        for (int off = 16; off; off >>= 1) sc += __shfl_xor_sync(0xffffffffu, sc, off);

        float al = (lane < Lz) ? slog[lane] : -1e30f;
        for (int t = 1; t < Tz; ++t) {
            float lg = (lane < Lz) ? slog[t*Lz + lane] : 0.f;
            float vals[Lz];
            float m1 = -1e30f;
            #pragma unroll
            for (int i = 0; i < Lz; ++i) {
                float ai = __shfl_sync(0xffffffffu, al, i);
                float x1 = ai + tr[i];
                vals[i] = x1;
                m1 = fmaxf(m1, x1);
            }
            float s = 0.f;
            #pragma unroll
            for (int i = 0; i < Lz; ++i) s += expf(vals[i] - m1);
            float nal = m1 + logf(s) + lg;
            if (lane < Lz && t < len) al = nal;
        }
        float m = -1e30f;
        #pragma unroll
        for (int i = 0; i < Lz; ++i) m = fmaxf(m, __shfl_sync(0xffffffffu, al, i));
        float s = 0.f;
        #pragma unroll
        for (int i = 0; i < Lz; ++i) s += expf(__shfl_sync(0xffffffffu, al, i) - m);
        float lognorm = m + logf(s);
        if (lane == 0) {
            out[LL0 + b] = sc - lognorm;
            out[LENS0 + b] = (float)len;
        }
    } else {
        float av = (lane < Lz) ? slog[lane] : -1e30f;
        for (int t = 1; t < Tz; ++t) {
            float lg = (lane < Lz) ? slog[t*Lz + lane] : 0.f;
            float m2 = -1e30f;
            int arg = 0;
            #pragma unroll
            for (int i = 0; i < Lz; ++i) {
                float vi = __shfl_sync(0xffffffffu, av, i);
                float x2 = vi + tr[i];
                if (x2 > m2) { m2 = x2; arg = i; }
            }
            float nav = m2 + lg;
            bool act = (t < len);
            if (lane < Lz) {
                if (act) {
                    av = nav;
                    bps[t-1][lane] = (unsigned char)arg;
                } else {
                    bps[t-1][lane] = (unsigned char)lane;
                }
            }
        }
        __syncwarp();
        float bestv = -1e30f; int bestidx = 0;
        #pragma unroll
        for (int i = 0; i < Lz; ++i) {
            float vi = __shfl_sync(0xffffffffu, av, i);
            if (vi > bestv) { bestv = vi; bestidx = i; }
        }
        if (lane == 0) {
            int tag = bestidx;
            out[TAGS0 + b*Tz + 255] = (float)tag;
            for (int k = 254; k >= 0; --k) {
                tag = bps[k][tag];
                out[TAGS0 + b*Tz + k] = (float)tag;
            }
        }
    }
}

// ---------------- launch ----------------
extern "C" void kernel_launch(void* const* d_in, const int* in_sizes, int n_in,
                              void* d_out, int out_size) {
    const int*   chars    = (const int*)d_in[0];
    const int*   words    = (const int*)d_in[1];
    const int*   labels   = (const int*)d_in[2];
    const float* char_emb = (const float*)d_in[3];
    const float* word_emb = (const float*)d_in[4];
    const float* W_word   = (const float*)d_in[5];
    const float* Wi_f     = (const float*)d_in[6];
    const float* Wh_f     = (const float*)d_in[7];
    const float* b_f      = (const float*)d_in[8];
    const float* Wi_b     = (const float*)d_in[9];
    const float* Wh_b     = (const float*)d_in[10];
    const float* b_b      = (const float*)d_in[11];
    const float* W_out    = (const float*)d_in[12];
    const float* b_out    = (const float*)d_in[13];
    const float* trans    = (const float*)d_in[14];
    float* out = (float*)d_out;

    cudaFuncSetAttribute(embed_kernel, cudaFuncAttributeMaxDynamicSharedMemorySize, 51200);
    cudaFuncSetAttribute(lstm_kernel,  cudaFuncAttributeMaxDynamicSharedMemorySize, 73728);

    init_kernel<<<1, 1>>>();
    embed_kernel<<<128, 256, 51200>>>(chars, words, char_emb, word_emb, W_word);
    gemm_zx_kernel<<<dim3(128, 16), 256>>>(Wi_f, Wi_b, b_f, b_b);
    lstm_kernel<<<128, 256, 73728>>>(Wh_f, Wh_b);
    logits_kernel<<<128, 128>>>(W_out, b_out, out);
    crf_kernel<<<Bz, 64>>>(chars, labels, trans, out);
}